// round 16
// baseline (speedup 1.0000x reference)
#include <cuda_runtime.h>
#include <cuda_fp16.h>
#include <math.h>
#include <stdint.h>

#define TT   1024
#define HH   2048
#define MI   1408
#define EE   32
#define KTOP 6
#define MSHD 2816
#define NA   (TT * KTOP)
#define N_X  (TT * HH)

// ---------------- scratch ---------------------------------------------------
__device__ __align__(16) __half g_x_h[N_X];
__device__ __align__(16) __half g_act[(size_t)NA * MI];
__device__ __align__(16) __half g_shact[(size_t)TT * MSHD];
__device__ float g_topkw[NA];
__device__ int   g_cnt[EE];
__device__ int   g_list[EE * TT];

// ---------------- helpers ----------------------------------------------------
__device__ __forceinline__ uint32_t s2u(const void* p) {
    uint32_t a;
    asm("{ .reg .u64 t; cvta.to.shared.u64 t, %1; cvt.u32.u64 %0, t; }"
        : "=r"(a) : "l"(p));
    return a;
}
__device__ __forceinline__ uint32_t pk(float lo, float hi) {
    uint32_t r;
    asm("cvt.rn.f16x2.f32 %0, %1, %2;" : "=r"(r) : "f"(hi), "f"(lo));
    return r;
}
__device__ __forceinline__ uint4 pk4(float4 a, float4 b) {
    return make_uint4(pk(a.x, a.y), pk(a.z, a.w), pk(b.x, b.y), pk(b.z, b.w));
}
__device__ __forceinline__ void mma16(float* c, const uint32_t* a,
                                      uint32_t b0, uint32_t b1)
{
    asm volatile(
      "mma.sync.aligned.m16n8k16.row.col.f32.f16.f16.f32 "
      "{%0,%1,%2,%3}, {%4,%5,%6,%7}, {%8,%9}, {%0,%1,%2,%3};"
      : "+f"(c[0]), "+f"(c[1]), "+f"(c[2]), "+f"(c[3])
      : "r"(a[0]), "r"(a[1]), "r"(a[2]), "r"(a[3]), "r"(b0), "r"(b1));
}
__device__ __forceinline__ void ldsm4(uint32_t* r, uint32_t addr) {
    asm volatile("ldmatrix.sync.aligned.m8n8.x4.shared.b16 {%0,%1,%2,%3}, [%4];"
                 : "=r"(r[0]), "=r"(r[1]), "=r"(r[2]), "=r"(r[3]) : "r"(addr));
}
__device__ __forceinline__ void ldsm4t(uint32_t* r, uint32_t addr) {
    asm volatile("ldmatrix.sync.aligned.m8n8.x4.trans.shared.b16 {%0,%1,%2,%3}, [%4];"
                 : "=r"(r[0]), "=r"(r[1]), "=r"(r[2]), "=r"(r[3]) : "r"(addr));
}
__device__ __forceinline__ void cpa16(uint32_t dst, const void* src) {
    asm volatile("cp.async.cg.shared.global [%0], [%1], 16;"
                 :: "r"(dst), "l"(src) : "memory");
}
__device__ __forceinline__ void cpa16z(uint32_t dst, const void* src, int sz) {
    asm volatile("cp.async.cg.shared.global [%0], [%1], 16, %2;"
                 :: "r"(dst), "l"(src), "r"(sz) : "memory");
}
__device__ __forceinline__ void red2(float* p, float v0, float v1) {
    asm volatile("red.global.add.v2.f32 [%0], {%1, %2};"
                 :: "l"(p), "f"(v0), "f"(v1) : "memory");
}
#define CP_COMMIT asm volatile("cp.async.commit_group;" ::: "memory")
#define CP_WAIT1  asm volatile("cp.async.wait_group 1;"  ::: "memory")
#define CP_WAIT2  asm volatile("cp.async.wait_group 2;"  ::: "memory")

// A tile SMEM: rows of 32 halfs = 64B, swizzle: chunk ^= (row>>1)&3
__device__ __forceinline__ uint32_t aoff(int row, int chunk) {
    return (uint32_t)(row * 64 + ((chunk ^ ((row >> 1) & 3)) << 4));
}
// B fp16 tile (row bytes RB = 128 or 256): row = k, swizzle: chunk ^= k&7
__device__ __forceinline__ uint32_t boff(int k, int chunk, int RB) {
    return (uint32_t)(k * RB + (((chunk ^ (k & 7))) << 4));
}

// SMEM map: A fp16 4 stages [0,32768), B fp32 3 stages [32768, 81920),
// B fp16 double buffer [81920, 98304)
#define OFF_B32 32768u
#define OFF_B16 81920u
#define SMEM_SZ 98304

// ---------------- tiny kernels ----------------------------------------------
__global__ void zero_cnt_kernel() {
    if (threadIdx.x < EE) g_cnt[threadIdx.x] = 0;
}

__global__ void cvt_kernel(const float4* __restrict__ src,
                           uint4* __restrict__ dst, int n8)
{
    int i = blockIdx.x * blockDim.x + threadIdx.x;
    if (i >= n8) return;
    float4 a = __ldcs(&src[2 * i]);
    float4 b = __ldcs(&src[2 * i + 1]);
    __stcs(&dst[i], pk4(a, b));
}

__global__ void router_kernel(const float* __restrict__ x,
                              const float* __restrict__ wr,
                              const float* __restrict__ bias)
{
    __shared__ float s_sfc[8][32];
    __shared__ float s_sc[8][32];
    int warp = threadIdx.x >> 5, lane = threadIdx.x & 31;
    int t = blockIdx.x * 8 + warp;
    const float* xr = x + (size_t)t * HH;

    float acc = 0.f;
#pragma unroll 8
    for (int h = 0; h < HH; ++h) acc = fmaf(xr[h], wr[h * EE + lane], acc);

    float sc = 1.f / (1.f + expf(-acc));
    s_sc[warp][lane]  = sc;
    s_sfc[warp][lane] = sc + bias[lane];
    __syncwarp();

    if (lane == 0) {
        float gsc[8];
#pragma unroll
        for (int g = 0; g < 8; ++g) {
            const float* v = &s_sfc[warp][g * 4];
            float m1 = -INFINITY; int i1 = 0;
            for (int j = 0; j < 4; ++j) if (v[j] > m1) { m1 = v[j]; i1 = j; }
            float m2 = -INFINITY;
            for (int j = 0; j < 4; ++j) if (j != i1 && v[j] > m2) m2 = v[j];
            gsc[g] = m1 + m2;
        }
        unsigned gsel = 0;
        for (int it = 0; it < 4; ++it) {
            float best = -INFINITY; int bi = 0;
            for (int g = 0; g < 8; ++g)
                if (!((gsel >> g) & 1) && gsc[g] > best) { best = gsc[g]; bi = g; }
            gsel |= 1u << bi;
        }
        float msk[32];
        for (int e = 0; e < 32; ++e)
            msk[e] = ((gsel >> (e >> 2)) & 1) ? s_sfc[warp][e] : -INFINITY;
        for (int k = 0; k < KTOP; ++k) {
            float best = -INFINITY; int bi = 0;
            for (int e = 0; e < 32; ++e)
                if (msk[e] > best) { best = msk[e]; bi = e; }
            msk[bi] = -INFINITY;
            int rowid = t * KTOP + k;
            g_topkw[rowid] = s_sc[warp][bi];
            int pos = atomicAdd(&g_cnt[bi], 1);
            g_list[bi * TT + pos] = rowid;
        }
    }
}

// =============================================================================
// Fused gate+up GEMM, fp32 weights staged directly, pipelined SMEM cvt.
// Tile MT x 64N, BK=32, 8 warps (4m x 2n). MT=128 full tiles, MT=64 remainder.
// REM: row0 = (cnt&~127) + by*64, guard row0 < cnt. Full: row0+128 <= cnt.
// =============================================================================
template<int MT, bool REM>
__global__ void __launch_bounds__(256, 2)
gu_hgemm(const __half* __restrict__ A, const float* __restrict__ Bg_all,
         const float* __restrict__ Bu_all, __half* __restrict__ C,
         const int* __restrict__ list, const int* __restrict__ cnts,
         int K, int N, int rowDiv, int fixedCnt)
{
    constexpr int MF = MT / 64;    // A fragments per warp (m dim): 2 or 1
    extern __shared__ __align__(16) char sm[];
    int e = blockIdx.z;
    int cnt = cnts ? cnts[e] : fixedCnt;
    int row0;
    if (REM) {
        row0 = (cnt & ~127) + blockIdx.y * 64;
        if (row0 >= cnt) return;
    } else {
        row0 = blockIdx.y * 128;
        if (row0 + MT > cnt) return;
    }
    int col0 = blockIdx.x * 64;
    const float* Bg = Bg_all + (size_t)e * K * N + col0;
    const float* Bu = Bu_all + (size_t)e * K * N + col0;

    uint32_t sb = s2u(sm);
    int tid = threadIdx.x, lane = tid & 31, w = tid >> 5;
    int l4 = lane & 3, g = lane >> 2;
    int wm = (w >> 1) * (MT / 4), wn = (w & 1) * 32;

    // ---- A cp.async map (fp16 from source) ----
    int rA = tid >> 2, cA = tid & 3;
    const __half* pA0 = A; const __half* pA1 = A;
    int szA0 = 0, szA1 = 0;
    {
        int gi = row0 + rA;
        if (gi < cnt) {
            int idx = list ? list[e * TT + gi] : gi;
            pA0 = A + (size_t)(idx / rowDiv) * K + 8 * cA; szA0 = 16;
        }
        if (MT == 128) {
            gi = row0 + rA + 64;
            if (gi < cnt) {
                int idx = list ? list[e * TT + gi] : gi;
                pA1 = A + (size_t)(idx / rowDiv) * K + 8 * cA; szA1 = 16;
            }
        }
    }
    uint32_t dA0 = aoff(rA, cA), dA1 = aoff(rA + 64, cA);

    // ---- B fp32 cp.async map ----
    int kS = tid >> 3, cS = tid & 7;
    const float* pBg0 = Bg + (size_t)kS * N + 4 * cS;
    const float* pBg1 = Bg + (size_t)kS * N + 4 * (cS + 8);
    const float* pBu0 = Bu + (size_t)kS * N + 4 * cS;
    const float* pBu1 = Bu + (size_t)kS * N + 4 * (cS + 8);
    uint32_t dB0 = (uint32_t)(kS * 256 + cS * 16);
    uint32_t dB1 = (uint32_t)(kS * 256 + (cS + 8) * 16);

#define GU_ISSUE(S4, S3) {                                                    \
        uint32_t soA = (uint32_t)(S4) * 8192u;                                \
        uint32_t soB = OFF_B32 + (uint32_t)(S3) * 16384u;                     \
        cpa16z(sb + soA + dA0, pA0, szA0);                                    \
        if (MT == 128) cpa16z(sb + soA + dA1, pA1, szA1);                     \
        cpa16(sb + soB + dB0, pBg0);                                          \
        cpa16(sb + soB + dB1, pBg1);                                          \
        cpa16(sb + soB + 8192 + dB0, pBu0);                                   \
        cpa16(sb + soB + 8192 + dB1, pBu1);                                   \
        pA0 += 32; pA1 += 32;                                                 \
        pBg0 += (size_t)32 * N; pBg1 += (size_t)32 * N;                       \
        pBu0 += (size_t)32 * N; pBu1 += (size_t)32 * N;                       \
        CP_COMMIT; }

#define CVT_GU(S3, BF) {                                                      \
        uint32_t b32 = OFF_B32 + (uint32_t)(S3) * 16384u                      \
                     + (uint32_t)(kS * 256 + cS * 32);                        \
        uint32_t b16 = OFF_B16 + (uint32_t)(BF) * 8192u;                      \
        const float4* sg = (const float4*)(sm + b32);                         \
        float4 va0 = sg[0], va1 = sg[1];                                      \
        *(uint4*)(sm + b16 + boff(kS, cS, 128)) = pk4(va0, va1);              \
        const float4* su = (const float4*)(sm + b32 + 8192);                  \
        float4 vb0 = su[0], vb1 = su[1];                                      \
        *(uint4*)(sm + b16 + 4096 + boff(kS, cS, 128)) = pk4(vb0, vb1); }

    // ---- ldmatrix lane addresses ----
    uint32_t adA[2][2], adB[2][2];
    {
        int rl = (lane & 7) + ((lane >> 3) & 1) * 8;
        int kcb = lane >> 4;
#pragma unroll
        for (int mf = 0; mf < MF; ++mf) {
            int row = wm + mf * 16 + rl;
#pragma unroll
            for (int kq = 0; kq < 2; ++kq)
                adA[mf][kq] = sb + aoff(row, kq * 2 + kcb);
        }
#pragma unroll
        for (int nf2 = 0; nf2 < 2; ++nf2) {
            int cb = (wn >> 3) + nf2 * 2 + (lane >> 4);
#pragma unroll
            for (int kq = 0; kq < 2; ++kq) {
                int k = kq * 16 + rl;
                adB[nf2][kq] = sb + OFF_B16 + boff(k, cb, 128);
            }
        }
    }

    float accg[MF][4][4], accu[MF][4][4];
#pragma unroll
    for (int a = 0; a < MF; ++a)
#pragma unroll
        for (int b = 0; b < 4; ++b)
#pragma unroll
            for (int c = 0; c < 4; ++c) { accg[a][b][c] = 0.f; accu[a][b][c] = 0.f; }

    const int nIter = K / 32;

    GU_ISSUE(0, 0);
    GU_ISSUE(1, 1);
    GU_ISSUE(2, 2);
    CP_WAIT2;
    __syncthreads();
    CVT_GU(0, 0);

    int c3 = 1, i4 = 0, bb = 0, j4 = 3, j3 = 0;
    for (int it = 0; it < nIter; ++it) {
        CP_WAIT1;
        __syncthreads();
        if (it + 3 < nIter) { GU_ISSUE(j4, j3); } else { CP_COMMIT; }
        if (it + 1 < nIter) CVT_GU(c3, bb ^ 1);

        uint32_t poA = (uint32_t)i4 * 8192u;
        uint32_t poB = (uint32_t)bb * 8192u;
#pragma unroll
        for (int kq = 0; kq < 2; ++kq) {
            uint32_t af[MF][4], b0[4], b1[4];
#pragma unroll
            for (int mf = 0; mf < MF; ++mf) ldsm4(af[mf], adA[mf][kq] + poA);
            ldsm4t(b0, adB[0][kq] + poB);
            ldsm4t(b1, adB[1][kq] + poB);
#pragma unroll
            for (int mf = 0; mf < MF; ++mf) {
                mma16(accg[mf][0], af[mf], b0[0], b0[1]);
                mma16(accg[mf][1], af[mf], b0[2], b0[3]);
                mma16(accg[mf][2], af[mf], b1[0], b1[1]);
                mma16(accg[mf][3], af[mf], b1[2], b1[3]);
            }
            ldsm4t(b0, adB[0][kq] + poB + 4096);
            ldsm4t(b1, adB[1][kq] + poB + 4096);
#pragma unroll
            for (int mf = 0; mf < MF; ++mf) {
                mma16(accu[mf][0], af[mf], b0[0], b0[1]);
                mma16(accu[mf][1], af[mf], b0[2], b0[3]);
                mma16(accu[mf][2], af[mf], b1[0], b1[1]);
                mma16(accu[mf][3], af[mf], b1[2], b1[3]);
            }
        }
        if (++c3 == 3) c3 = 0;
        if (++i4 == 4) i4 = 0;
        bb ^= 1;
        if (++j4 == 4) j4 = 0;
        if (++j3 == 3) j3 = 0;
    }

    // epilogue: act = silu(g) * u  (fp16 store)
#pragma unroll
    for (int mf = 0; mf < MF; ++mf)
#pragma unroll
        for (int h = 0; h < 2; ++h) {
            int rl = wm + mf * 16 + g + h * 8;
            int gi = row0 + rl;
            if (gi >= cnt) continue;
            int idx = list ? list[e * TT + gi] : gi;
            __half* Cr = C + (size_t)idx * N + col0;
#pragma unroll
            for (int nf = 0; nf < 4; ++nf) {
                int col = wn + nf * 8 + 2 * l4;
                float g0 = accg[mf][nf][2 * h + 0];
                float g1 = accg[mf][nf][2 * h + 1];
                float u0 = accu[mf][nf][2 * h + 0];
                float u1 = accu[mf][nf][2 * h + 1];
                float s0 = g0 / (1.f + __expf(-g0)) * u0;
                float s1 = g1 / (1.f + __expf(-g1)) * u1;
                *(uint32_t*)(Cr + col) = pk(s0, s1);
            }
        }
#undef GU_ISSUE
#undef CVT_GU
}

// =============================================================================
// Down GEMM, fp32 weights staged directly, pipelined SMEM cvt.
// Tile MT x 128N, BK=32, 8 warps (2m x 4n). MT=128 full, MT=64 remainder.
// out[idx/kdiv] += v * (rowScale ? rowScale[idx] : 1)  (red.v2)
// =============================================================================
template<int MT, bool REM>
__global__ void __launch_bounds__(256, 2)
dn_hgemm(const __half* __restrict__ A, const float* __restrict__ Bb,
         float* __restrict__ C,
         const int* __restrict__ list, const int* __restrict__ cnts,
         const float* __restrict__ rowScale,
         int K, int N, int fixedCnt, int kdiv)
{
    constexpr int MF = MT / 32;   // 4 or 2
    extern __shared__ __align__(16) char sm[];
    int e = blockIdx.z;
    int cnt = cnts ? cnts[e] : fixedCnt;
    int row0;
    if (REM) {
        row0 = (cnt & ~127) + blockIdx.y * 64;
        if (row0 >= cnt) return;
    } else {
        row0 = blockIdx.y * 128;
        if (row0 + MT > cnt) return;
    }
    int col0 = blockIdx.x * 128;
    const float* B = Bb + (size_t)e * K * N + col0;

    uint32_t sb = s2u(sm);
    int tid = threadIdx.x, lane = tid & 31, w = tid >> 5;
    int l4 = lane & 3, g = lane >> 2;
    int wm = (w & 1) * (MT / 2), wn = (w >> 1) * 32;

    int rA = tid >> 2, cA = tid & 3;
    const __half* pA0 = A; const __half* pA1 = A;
    int szA0 = 0, szA1 = 0;
    {
        int gi = row0 + rA;
        if (gi < cnt) {
            int idx = list ? list[e * TT + gi] : gi;
            pA0 = A + (size_t)idx * K + 8 * cA; szA0 = 16;
        }
        if (MT == 128) {
            gi = row0 + rA + 64;
            if (gi < cnt) {
                int idx = list ? list[e * TT + gi] : gi;
                pA1 = A + (size_t)idx * K + 8 * cA; szA1 = 16;
            }
        }
    }
    uint32_t dA0 = aoff(rA, cA), dA1 = aoff(rA + 64, cA);

    int kS = tid >> 3, cS = tid & 7;
    const float* pB0 = B + (size_t)kS * N + 4 * cS;
    const float* pB1 = B + (size_t)kS * N + 4 * (cS + 8);
    const float* pB2 = B + (size_t)kS * N + 4 * (cS + 16);
    const float* pB3 = B + (size_t)kS * N + 4 * (cS + 24);
    uint32_t dB0 = (uint32_t)(kS * 512 + cS * 16);
    uint32_t dB1 = dB0 + 128, dB2 = dB0 + 256, dB3 = dB0 + 384;

#define DN_ISSUE(S4, S3) {                                                    \
        uint32_t soA = (uint32_t)(S4) * 8192u;                                \
        uint32_t soB = OFF_B32 + (uint32_t)(S3) * 16384u;                     \
        cpa16z(sb + soA + dA0, pA0, szA0);                                    \
        if (MT == 128) cpa16z(sb + soA + dA1, pA1, szA1);                     \
        cpa16(sb + soB + dB0, pB0);                                           \
        cpa16(sb + soB + dB1, pB1);                                           \
        cpa16(sb + soB + dB2, pB2);                                           \
        cpa16(sb + soB + dB3, pB3);                                           \
        pA0 += 32; pA1 += 32;                                                 \
        pB0 += (size_t)32 * N; pB1 += (size_t)32 * N;                         \
        pB2 += (size_t)32 * N; pB3 += (size_t)32 * N;                         \
        CP_COMMIT; }

#define CVT_DN(S3, BF) {                                                      \
        uint32_t b32 = OFF_B32 + (uint32_t)(S3) * 16384u + (uint32_t)(kS * 512); \
        uint32_t b16 = OFF_B16 + (uint32_t)(BF) * 8192u;                      \
        const float4* s0p = (const float4*)(sm + b32 + cS * 32);              \
        float4 va0 = s0p[0], va1 = s0p[1];                                    \
        *(uint4*)(sm + b16 + boff(kS, cS, 256)) = pk4(va0, va1);              \
        const float4* s1p = (const float4*)(sm + b32 + (cS + 8) * 32);        \
        float4 vb0 = s1p[0], vb1 = s1p[1];                                    \
        *(uint4*)(sm + b16 + boff(kS, cS + 8, 256)) = pk4(vb0, vb1); }

    uint32_t adA[4][2], adB[2][2];
    {
        int rl = (lane & 7) + ((lane >> 3) & 1) * 8;
        int kcb = lane >> 4;
#pragma unroll
        for (int mf = 0; mf < MF; ++mf) {
            int row = wm + mf * 16 + rl;
#pragma unroll
            for (int kq = 0; kq < 2; ++kq)
                adA[mf][kq] = sb + aoff(row, kq * 2 + kcb);
        }
#pragma unroll
        for (int nf2 = 0; nf2 < 2; ++nf2) {
            int cb = (wn >> 3) + nf2 * 2 + (lane >> 4);
#pragma unroll
            for (int kq = 0; kq < 2; ++kq) {
                int k = kq * 16 + rl;
                adB[nf2][kq] = sb + OFF_B16 + boff(k, cb, 256);
            }
        }
    }

    float acc[MF][4][4];
#pragma unroll
    for (int a = 0; a < MF; ++a)
#pragma unroll
        for (int b = 0; b < 4; ++b)
#pragma unroll
            for (int c = 0; c < 4; ++c) acc[a][b][c] = 0.f;

    const int nIter = K / 32;

    DN_ISSUE(0, 0);
    DN_ISSUE(1, 1);
    DN_ISSUE(2, 2);
    CP_WAIT2;
    __syncthreads();
    CVT_DN(0, 0);

    int c3 = 1, i4 = 0, bb = 0, j4 = 3, j3 = 0;
    for (int it = 0; it < nIter; ++it) {
        CP_WAIT1;
        __syncthreads();
        if (it + 3 < nIter) { DN_ISSUE(j4, j3); } else { CP_COMMIT; }
        if (it + 1 < nIter) CVT_DN(c3, bb ^ 1);

        uint32_t poA = (uint32_t)i4 * 8192u;
        uint32_t poB = (uint32_t)bb * 8192u;
#pragma unroll
        for (int kq = 0; kq < 2; ++kq) {
            uint32_t b0[4], b1[4];
            ldsm4t(b0, adB[0][kq] + poB);
            ldsm4t(b1, adB[1][kq] + poB);
#pragma unroll
            for (int mf = 0; mf < MF; ++mf) {
                uint32_t a[4];
                ldsm4(a, adA[mf][kq] + poA);
                mma16(acc[mf][0], a, b0[0], b0[1]);
                mma16(acc[mf][1], a, b0[2], b0[3]);
                mma16(acc[mf][2], a, b1[0], b1[1]);
                mma16(acc[mf][3], a, b1[2], b1[3]);
            }
        }
        if (++c3 == 3) c3 = 0;
        if (++i4 == 4) i4 = 0;
        bb ^= 1;
        if (++j4 == 4) j4 = 0;
        if (++j3 == 3) j3 = 0;
    }

    // epilogue
#pragma unroll
    for (int mf = 0; mf < MF; ++mf)
#pragma unroll
        for (int h = 0; h < 2; ++h) {
            int rl = wm + mf * 16 + g + h * 8;
            int gi = row0 + rl;
            if (gi >= cnt) continue;
            int idx = list ? list[e * TT + gi] : gi;
            float s = 1.f;
            if (rowScale) s = rowScale[idx];
            float* Cr = C + (size_t)(idx / kdiv) * N + col0;
#pragma unroll
            for (int nf = 0; nf < 4; ++nf) {
                int col = wn + nf * 8 + 2 * l4;
                red2(Cr + col, acc[mf][nf][2 * h] * s, acc[mf][nf][2 * h + 1] * s);
            }
        }
#undef DN_ISSUE
#undef CVT_DN
}

// ---------------- launch ------------------------------------------------------
extern "C" void kernel_launch(void* const* d_in, const int* in_sizes, int n_in,
                              void* d_out, int out_size)
{
    const float* x      = (const float*)d_in[0];
    const float* wr     = (const float*)d_in[1];
    const float* bias   = (const float*)d_in[2];
    const float* gate_w = (const float*)d_in[3];
    const float* up_w   = (const float*)d_in[4];
    const float* down_w = (const float*)d_in[5];
    const float* shg    = (const float*)d_in[6];
    const float* shu    = (const float*)d_in[7];
    const float* shd    = (const float*)d_in[8];
    float* out = (float*)d_out;

    void *p_act, *p_shact, *p_w, *p_cnt, *p_list, *p_xh;
    cudaGetSymbolAddress(&p_act,   g_act);
    cudaGetSymbolAddress(&p_shact, g_shact);
    cudaGetSymbolAddress(&p_w,     g_topkw);
    cudaGetSymbolAddress(&p_cnt,   g_cnt);
    cudaGetSymbolAddress(&p_list,  g_list);
    cudaGetSymbolAddress(&p_xh,    g_x_h);

    cudaFuncSetAttribute(gu_hgemm<128,false>, cudaFuncAttributeMaxDynamicSharedMemorySize, SMEM_SZ);
    cudaFuncSetAttribute(gu_hgemm<64,true>,   cudaFuncAttributeMaxDynamicSharedMemorySize, SMEM_SZ);
    cudaFuncSetAttribute(dn_hgemm<128,false>, cudaFuncAttributeMaxDynamicSharedMemorySize, SMEM_SZ);
    cudaFuncSetAttribute(dn_hgemm<64,true>,   cudaFuncAttributeMaxDynamicSharedMemorySize, SMEM_SZ);

    cudaStream_t s1;
    cudaStreamCreateWithFlags(&s1, cudaStreamNonBlocking);
    cudaEvent_t evFork, evX, evRt, evJoin;
    cudaEventCreateWithFlags(&evFork, cudaEventDisableTiming);
    cudaEventCreateWithFlags(&evX,    cudaEventDisableTiming);
    cudaEventCreateWithFlags(&evRt,   cudaEventDisableTiming);
    cudaEventCreateWithFlags(&evJoin, cudaEventDisableTiming);

    cudaEventRecord(evFork, 0);
    cudaStreamWaitEvent(s1, evFork, 0);

    // ---- s1: zero out, router; then shared chain (after x is converted) ----
    cudaMemsetAsync(out, 0, (size_t)TT * HH * sizeof(float), s1);
    zero_cnt_kernel<<<1, 32, 0, s1>>>();
    router_kernel<<<TT / 8, 256, 0, s1>>>(x, wr, bias);
    cudaEventRecord(evRt, s1);

    // ---- s0: convert x to fp16 ----
    cvt_kernel<<<(N_X / 8 + 255) / 256, 256>>>(
        (const float4*)x, (uint4*)p_xh, N_X / 8);
    cudaEventRecord(evX, 0);

    // ---- s1: shared experts (cnt = TT, all full tiles) ----
    cudaStreamWaitEvent(s1, evX, 0);
    gu_hgemm<128,false><<<dim3(MSHD / 64, TT / 128, 1), 256, SMEM_SZ, s1>>>(
        (const __half*)p_xh, shg, shu, (__half*)p_shact,
        nullptr, nullptr, HH, MSHD, 1, TT);
    dn_hgemm<128,false><<<dim3(HH / 128, TT / 128, 1), 256, SMEM_SZ, s1>>>(
        (const __half*)p_shact, shd, out,
        nullptr, nullptr, nullptr, MSHD, HH, TT, 1);
    cudaEventRecord(evJoin, s1);

    // ---- s0: routed experts, full + remainder tiles ----
    cudaStreamWaitEvent(0, evRt, 0);
    gu_hgemm<128,false><<<dim3(MI / 64, TT / 128, EE), 256, SMEM_SZ>>>(
        (const __half*)p_xh, gate_w, up_w, (__half*)p_act,
        (const int*)p_list, (const int*)p_cnt, HH, MI, KTOP, 0);
    gu_hgemm<64,true><<<dim3(MI / 64, 2, EE), 256, SMEM_SZ>>>(
        (const __half*)p_xh, gate_w, up_w, (__half*)p_act,
        (const int*)p_list, (const int*)p_cnt, HH, MI, KTOP, 0);
    dn_hgemm<128,false><<<dim3(HH / 128, TT / 128, EE), 256, SMEM_SZ>>>(
        (const __half*)p_act, down_w, out,
        (const int*)p_list, (const int*)p_cnt, (const float*)p_w,
        MI, HH, 0, KTOP);
    dn_hgemm<64,true><<<dim3(HH / 128, 2, EE), 256, SMEM_SZ>>>(
        (const __half*)p_act, down_w, out,
        (const int*)p_list, (const int*)p_cnt, (const float*)p_w,
        MI, HH, 0, KTOP);

    // join s1 into capture
    cudaStreamWaitEvent(0, evJoin, 0);
}

// round 17
// speedup vs baseline: 1.1250x; 1.1250x over previous
#include <cuda_runtime.h>
#include <cuda_fp16.h>
#include <math.h>
#include <stdint.h>

#define TT   1024
#define HH   2048
#define MI   1408
#define EE   32
#define KTOP 6
#define MSHD 2816
#define NA   (TT * KTOP)
#define N_X  (TT * HH)

// ---------------- scratch ---------------------------------------------------
__device__ __align__(16) __half g_x_h[N_X];
__device__ __align__(16) __half g_act[(size_t)NA * MI];
__device__ __align__(16) __half g_shact[(size_t)TT * MSHD];
__device__ float g_topkw[NA];
__device__ int   g_cnt[EE];
__device__ int   g_list[EE * TT];

// ---------------- helpers ----------------------------------------------------
__device__ __forceinline__ uint32_t s2u(const void* p) {
    uint32_t a;
    asm("{ .reg .u64 t; cvta.to.shared.u64 t, %1; cvt.u32.u64 %0, t; }"
        : "=r"(a) : "l"(p));
    return a;
}
__device__ __forceinline__ uint32_t pk(float lo, float hi) {
    uint32_t r;
    asm("cvt.rn.f16x2.f32 %0, %1, %2;" : "=r"(r) : "f"(hi), "f"(lo));
    return r;
}
__device__ __forceinline__ uint4 pk4(float4 a, float4 b) {
    return make_uint4(pk(a.x, a.y), pk(a.z, a.w), pk(b.x, b.y), pk(b.z, b.w));
}
__device__ __forceinline__ void mma16(float* c, const uint32_t* a,
                                      uint32_t b0, uint32_t b1)
{
    asm volatile(
      "mma.sync.aligned.m16n8k16.row.col.f32.f16.f16.f32 "
      "{%0,%1,%2,%3}, {%4,%5,%6,%7}, {%8,%9}, {%0,%1,%2,%3};"
      : "+f"(c[0]), "+f"(c[1]), "+f"(c[2]), "+f"(c[3])
      : "r"(a[0]), "r"(a[1]), "r"(a[2]), "r"(a[3]), "r"(b0), "r"(b1));
}
__device__ __forceinline__ void ldsm4(uint32_t* r, uint32_t addr) {
    asm volatile("ldmatrix.sync.aligned.m8n8.x4.shared.b16 {%0,%1,%2,%3}, [%4];"
                 : "=r"(r[0]), "=r"(r[1]), "=r"(r[2]), "=r"(r[3]) : "r"(addr));
}
__device__ __forceinline__ void ldsm4t(uint32_t* r, uint32_t addr) {
    asm volatile("ldmatrix.sync.aligned.m8n8.x4.trans.shared.b16 {%0,%1,%2,%3}, [%4];"
                 : "=r"(r[0]), "=r"(r[1]), "=r"(r[2]), "=r"(r[3]) : "r"(addr));
}
__device__ __forceinline__ void cpa16(uint32_t dst, const void* src) {
    asm volatile("cp.async.cg.shared.global [%0], [%1], 16;"
                 :: "r"(dst), "l"(src) : "memory");
}
__device__ __forceinline__ void cpa16z(uint32_t dst, const void* src, int sz) {
    asm volatile("cp.async.cg.shared.global [%0], [%1], 16, %2;"
                 :: "r"(dst), "l"(src), "r"(sz) : "memory");
}
__device__ __forceinline__ void red2(float* p, float v0, float v1) {
    asm volatile("red.global.add.v2.f32 [%0], {%1, %2};"
                 :: "l"(p), "f"(v0), "f"(v1) : "memory");
}
#define CP_COMMIT asm volatile("cp.async.commit_group;" ::: "memory")
#define CP_WAIT1  asm volatile("cp.async.wait_group 1;"  ::: "memory")
#define CP_WAIT2  asm volatile("cp.async.wait_group 2;"  ::: "memory")

// A tile SMEM: rows of 32 halfs = 64B, swizzle: chunk ^= (row>>1)&3
__device__ __forceinline__ uint32_t aoff(int row, int chunk) {
    return (uint32_t)(row * 64 + ((chunk ^ ((row >> 1) & 3)) << 4));
}
// B fp16 tile (row bytes RB = 128 or 256): row = k, swizzle: chunk ^= k&7
__device__ __forceinline__ uint32_t boff(int k, int chunk, int RB) {
    return (uint32_t)(k * RB + (((chunk ^ (k & 7))) << 4));
}

// SMEM map: A fp16 4 stages [0,32768), B fp32 3 stages [32768, 81920),
// B fp16 double buffer [81920, 98304)
#define OFF_B32 32768u
#define OFF_B16 81920u
#define SMEM_SZ 98304

// ---------------- tiny kernels ----------------------------------------------
__global__ void zero_cnt_kernel() {
    if (threadIdx.x < EE) g_cnt[threadIdx.x] = 0;
}

__global__ void cvt_kernel(const float4* __restrict__ src,
                           uint4* __restrict__ dst, int n8)
{
    int i = blockIdx.x * blockDim.x + threadIdx.x;
    if (i >= n8) return;
    float4 a = __ldcs(&src[2 * i]);
    float4 b = __ldcs(&src[2 * i + 1]);
    __stcs(&dst[i], pk4(a, b));
}

__global__ void router_kernel(const float* __restrict__ x,
                              const float* __restrict__ wr,
                              const float* __restrict__ bias)
{
    __shared__ float s_sfc[8][32];
    __shared__ float s_sc[8][32];
    int warp = threadIdx.x >> 5, lane = threadIdx.x & 31;
    int t = blockIdx.x * 8 + warp;
    const float* xr = x + (size_t)t * HH;

    float acc = 0.f;
#pragma unroll 8
    for (int h = 0; h < HH; ++h) acc = fmaf(xr[h], wr[h * EE + lane], acc);

    float sc = 1.f / (1.f + expf(-acc));
    s_sc[warp][lane]  = sc;
    s_sfc[warp][lane] = sc + bias[lane];
    __syncwarp();

    if (lane == 0) {
        float gsc[8];
#pragma unroll
        for (int g = 0; g < 8; ++g) {
            const float* v = &s_sfc[warp][g * 4];
            float m1 = -INFINITY; int i1 = 0;
            for (int j = 0; j < 4; ++j) if (v[j] > m1) { m1 = v[j]; i1 = j; }
            float m2 = -INFINITY;
            for (int j = 0; j < 4; ++j) if (j != i1 && v[j] > m2) m2 = v[j];
            gsc[g] = m1 + m2;
        }
        unsigned gsel = 0;
        for (int it = 0; it < 4; ++it) {
            float best = -INFINITY; int bi = 0;
            for (int g = 0; g < 8; ++g)
                if (!((gsel >> g) & 1) && gsc[g] > best) { best = gsc[g]; bi = g; }
            gsel |= 1u << bi;
        }
        float msk[32];
        for (int e = 0; e < 32; ++e)
            msk[e] = ((gsel >> (e >> 2)) & 1) ? s_sfc[warp][e] : -INFINITY;
        for (int k = 0; k < KTOP; ++k) {
            float best = -INFINITY; int bi = 0;
            for (int e = 0; e < 32; ++e)
                if (msk[e] > best) { best = msk[e]; bi = e; }
            msk[bi] = -INFINITY;
            int rowid = t * KTOP + k;
            g_topkw[rowid] = s_sc[warp][bi];
            int pos = atomicAdd(&g_cnt[bi], 1);
            g_list[bi * TT + pos] = rowid;
        }
    }
}

// =============================================================================
// Fused gate+up GEMM, fp32 weights staged directly, pipelined SMEM cvt.
// Tile 128M x 64N, BK=32, 8 warps 4m x 2n. One barrier per iteration.
// =============================================================================
__global__ void __launch_bounds__(256, 2)
gu_hgemm(const __half* __restrict__ A, const float* __restrict__ Bg_all,
         const float* __restrict__ Bu_all, __half* __restrict__ C,
         const int* __restrict__ list, const int* __restrict__ cnts,
         int K, int N, int rowDiv, int fixedCnt)
{
    extern __shared__ __align__(16) char sm[];
    int e = blockIdx.z;
    int cnt = cnts ? cnts[e] : fixedCnt;
    int row0 = blockIdx.y * 128;
    if (row0 >= cnt) return;
    int col0 = blockIdx.x * 64;
    const float* Bg = Bg_all + (size_t)e * K * N + col0;
    const float* Bu = Bu_all + (size_t)e * K * N + col0;

    uint32_t sb = s2u(sm);
    int tid = threadIdx.x, lane = tid & 31, w = tid >> 5;
    int l4 = lane & 3, g = lane >> 2;
    int wm = (w >> 1) * 32, wn = (w & 1) * 32;

    int rA = tid >> 2, cA = tid & 3;
    const __half* pA0; const __half* pA1;
    int szA0 = 0, szA1 = 0;
    {
        int gi = row0 + rA;
        if (gi < cnt) {
            int idx = list ? list[e * TT + gi] : gi;
            pA0 = A + (size_t)(idx / rowDiv) * K + 8 * cA; szA0 = 16;
        } else pA0 = A;
        gi = row0 + rA + 64;
        if (gi < cnt) {
            int idx = list ? list[e * TT + gi] : gi;
            pA1 = A + (size_t)(idx / rowDiv) * K + 8 * cA; szA1 = 16;
        } else pA1 = A;
    }
    uint32_t dA0 = aoff(rA, cA), dA1 = aoff(rA + 64, cA);

    int kS = tid >> 3, cS = tid & 7;
    const float* pBg0 = Bg + (size_t)kS * N + 4 * cS;
    const float* pBg1 = Bg + (size_t)kS * N + 4 * (cS + 8);
    const float* pBu0 = Bu + (size_t)kS * N + 4 * cS;
    const float* pBu1 = Bu + (size_t)kS * N + 4 * (cS + 8);
    uint32_t dB0 = (uint32_t)(kS * 256 + cS * 16);
    uint32_t dB1 = (uint32_t)(kS * 256 + (cS + 8) * 16);

#define GU_ISSUE(S4, S3) {                                                    \
        uint32_t soA = (uint32_t)(S4) * 8192u;                                \
        uint32_t soB = OFF_B32 + (uint32_t)(S3) * 16384u;                     \
        cpa16z(sb + soA + dA0, pA0, szA0);                                    \
        cpa16z(sb + soA + dA1, pA1, szA1);                                    \
        cpa16(sb + soB + dB0, pBg0);                                          \
        cpa16(sb + soB + dB1, pBg1);                                          \
        cpa16(sb + soB + 8192 + dB0, pBu0);                                   \
        cpa16(sb + soB + 8192 + dB1, pBu1);                                   \
        pA0 += 32; pA1 += 32;                                                 \
        pBg0 += (size_t)32 * N; pBg1 += (size_t)32 * N;                       \
        pBu0 += (size_t)32 * N; pBu1 += (size_t)32 * N;                       \
        CP_COMMIT; }

#define CVT_GU(S3, BF) {                                                      \
        uint32_t b32 = OFF_B32 + (uint32_t)(S3) * 16384u                      \
                     + (uint32_t)(kS * 256 + cS * 32);                        \
        uint32_t b16 = OFF_B16 + (uint32_t)(BF) * 8192u;                      \
        const float4* sg = (const float4*)(sm + b32);                         \
        float4 va0 = sg[0], va1 = sg[1];                                      \
        *(uint4*)(sm + b16 + boff(kS, cS, 128)) = pk4(va0, va1);              \
        const float4* su = (const float4*)(sm + b32 + 8192);                  \
        float4 vb0 = su[0], vb1 = su[1];                                      \
        *(uint4*)(sm + b16 + 4096 + boff(kS, cS, 128)) = pk4(vb0, vb1); }

    uint32_t adA[2][2], adB[2][2];
    {
        int rl = (lane & 7) + ((lane >> 3) & 1) * 8;
        int kcb = lane >> 4;
#pragma unroll
        for (int mf = 0; mf < 2; ++mf) {
            int row = wm + mf * 16 + rl;
#pragma unroll
            for (int kq = 0; kq < 2; ++kq)
                adA[mf][kq] = sb + aoff(row, kq * 2 + kcb);
        }
#pragma unroll
        for (int nf2 = 0; nf2 < 2; ++nf2) {
            int cb = (wn >> 3) + nf2 * 2 + (lane >> 4);
#pragma unroll
            for (int kq = 0; kq < 2; ++kq) {
                int k = kq * 16 + rl;
                adB[nf2][kq] = sb + OFF_B16 + boff(k, cb, 128);
            }
        }
    }

    float accg[2][4][4], accu[2][4][4];
#pragma unroll
    for (int a = 0; a < 2; ++a)
#pragma unroll
        for (int b = 0; b < 4; ++b)
#pragma unroll
            for (int c = 0; c < 4; ++c) { accg[a][b][c] = 0.f; accu[a][b][c] = 0.f; }

    const int nIter = K / 32;

    GU_ISSUE(0, 0);
    GU_ISSUE(1, 1);
    GU_ISSUE(2, 2);
    CP_WAIT2;
    __syncthreads();
    CVT_GU(0, 0);

    int c3 = 1, i4 = 0, bb = 0, j4 = 3, j3 = 0;
    for (int it = 0; it < nIter; ++it) {
        CP_WAIT1;
        __syncthreads();
        if (it + 3 < nIter) { GU_ISSUE(j4, j3); } else { CP_COMMIT; }
        if (it + 1 < nIter) CVT_GU(c3, bb ^ 1);

        uint32_t poA = (uint32_t)i4 * 8192u;
        uint32_t poB = (uint32_t)bb * 8192u;
#pragma unroll
        for (int kq = 0; kq < 2; ++kq) {
            uint32_t a0[4], a1[4], b0[4], b1[4];
            ldsm4(a0, adA[0][kq] + poA);
            ldsm4(a1, adA[1][kq] + poA);
            ldsm4t(b0, adB[0][kq] + poB);
            ldsm4t(b1, adB[1][kq] + poB);
            mma16(accg[0][0], a0, b0[0], b0[1]);
            mma16(accg[0][1], a0, b0[2], b0[3]);
            mma16(accg[0][2], a0, b1[0], b1[1]);
            mma16(accg[0][3], a0, b1[2], b1[3]);
            mma16(accg[1][0], a1, b0[0], b0[1]);
            mma16(accg[1][1], a1, b0[2], b0[3]);
            mma16(accg[1][2], a1, b1[0], b1[1]);
            mma16(accg[1][3], a1, b1[2], b1[3]);
            ldsm4t(b0, adB[0][kq] + poB + 4096);
            ldsm4t(b1, adB[1][kq] + poB + 4096);
            mma16(accu[0][0], a0, b0[0], b0[1]);
            mma16(accu[0][1], a0, b0[2], b0[3]);
            mma16(accu[0][2], a0, b1[0], b1[1]);
            mma16(accu[0][3], a0, b1[2], b1[3]);
            mma16(accu[1][0], a1, b0[0], b0[1]);
            mma16(accu[1][1], a1, b0[2], b0[3]);
            mma16(accu[1][2], a1, b1[0], b1[1]);
            mma16(accu[1][3], a1, b1[2], b1[3]);
        }
        if (++c3 == 3) c3 = 0;
        if (++i4 == 4) i4 = 0;
        bb ^= 1;
        if (++j4 == 4) j4 = 0;
        if (++j3 == 3) j3 = 0;
    }

    // epilogue: act = silu(g) * u  (fp16 store)
#pragma unroll
    for (int mf = 0; mf < 2; ++mf)
#pragma unroll
        for (int h = 0; h < 2; ++h) {
            int rl = wm + mf * 16 + g + h * 8;
            int gi = row0 + rl;
            if (gi >= cnt) continue;
            int idx = list ? list[e * TT + gi] : gi;
            __half* Cr = C + (size_t)idx * N + col0;
#pragma unroll
            for (int nf = 0; nf < 4; ++nf) {
                int col = wn + nf * 8 + 2 * l4;
                float g0 = accg[mf][nf][2 * h + 0];
                float g1 = accg[mf][nf][2 * h + 1];
                float u0 = accu[mf][nf][2 * h + 0];
                float u1 = accu[mf][nf][2 * h + 1];
                float s0 = g0 / (1.f + __expf(-g0)) * u0;
                float s1 = g1 / (1.f + __expf(-g1)) * u1;
                *(uint32_t*)(Cr + col) = pk(s0, s1);
            }
        }
#undef GU_ISSUE
#undef CVT_GU
}

// =============================================================================
// Down GEMM, fp32 weights staged directly, pipelined SMEM cvt.
// Tile 128M x 128N, BK=32, 8 warps 2m x 4n. One barrier per iteration.
// ATOMIC=0: C[idx] = v. ATOMIC=1: out[idx/kdiv] += v * scale (red.v2).
// =============================================================================
template<int ATOMIC>
__global__ void __launch_bounds__(256, 2)
dn_hgemm(const __half* __restrict__ A, const float* __restrict__ Bb,
         float* __restrict__ C,
         const int* __restrict__ list, const int* __restrict__ cnts,
         const float* __restrict__ rowScale,
         int K, int N, int fixedCnt, int kdiv)
{
    extern __shared__ __align__(16) char sm[];
    int e = blockIdx.z;
    int cnt = cnts ? cnts[e] : fixedCnt;
    int row0 = blockIdx.y * 128;
    if (row0 >= cnt) return;
    int col0 = blockIdx.x * 128;
    const float* B = Bb + (size_t)e * K * N + col0;

    uint32_t sb = s2u(sm);
    int tid = threadIdx.x, lane = tid & 31, w = tid >> 5;
    int l4 = lane & 3, g = lane >> 2;
    int wm = (w & 1) * 64, wn = (w >> 1) * 32;

    int rA = tid >> 2, cA = tid & 3;
    const __half* pA0; const __half* pA1;
    int szA0 = 0, szA1 = 0;
    {
        int gi = row0 + rA;
        if (gi < cnt) {
            int idx = list ? list[e * TT + gi] : gi;
            pA0 = A + (size_t)idx * K + 8 * cA; szA0 = 16;
        } else pA0 = A;
        gi = row0 + rA + 64;
        if (gi < cnt) {
            int idx = list ? list[e * TT + gi] : gi;
            pA1 = A + (size_t)idx * K + 8 * cA; szA1 = 16;
        } else pA1 = A;
    }
    uint32_t dA0 = aoff(rA, cA), dA1 = aoff(rA + 64, cA);

    int kS = tid >> 3, cS = tid & 7;
    const float* pB0 = B + (size_t)kS * N + 4 * cS;
    const float* pB1 = B + (size_t)kS * N + 4 * (cS + 8);
    const float* pB2 = B + (size_t)kS * N + 4 * (cS + 16);
    const float* pB3 = B + (size_t)kS * N + 4 * (cS + 24);
    uint32_t dB0 = (uint32_t)(kS * 512 + cS * 16);
    uint32_t dB1 = dB0 + 128, dB2 = dB0 + 256, dB3 = dB0 + 384;

#define DN_ISSUE(S4, S3) {                                                    \
        uint32_t soA = (uint32_t)(S4) * 8192u;                                \
        uint32_t soB = OFF_B32 + (uint32_t)(S3) * 16384u;                     \
        cpa16z(sb + soA + dA0, pA0, szA0);                                    \
        cpa16z(sb + soA + dA1, pA1, szA1);                                    \
        cpa16(sb + soB + dB0, pB0);                                           \
        cpa16(sb + soB + dB1, pB1);                                           \
        cpa16(sb + soB + dB2, pB2);                                           \
        cpa16(sb + soB + dB3, pB3);                                           \
        pA0 += 32; pA1 += 32;                                                 \
        pB0 += (size_t)32 * N; pB1 += (size_t)32 * N;                         \
        pB2 += (size_t)32 * N; pB3 += (size_t)32 * N;                         \
        CP_COMMIT; }

#define CVT_DN(S3, BF) {                                                      \
        uint32_t b32 = OFF_B32 + (uint32_t)(S3) * 16384u + (uint32_t)(kS * 512); \
        uint32_t b16 = OFF_B16 + (uint32_t)(BF) * 8192u;                      \
        const float4* s0p = (const float4*)(sm + b32 + cS * 32);              \
        float4 va0 = s0p[0], va1 = s0p[1];                                    \
        *(uint4*)(sm + b16 + boff(kS, cS, 256)) = pk4(va0, va1);              \
        const float4* s1p = (const float4*)(sm + b32 + (cS + 8) * 32);        \
        float4 vb0 = s1p[0], vb1 = s1p[1];                                    \
        *(uint4*)(sm + b16 + boff(kS, cS + 8, 256)) = pk4(vb0, vb1); }

    uint32_t adA[4][2], adB[2][2];
    {
        int rl = (lane & 7) + ((lane >> 3) & 1) * 8;
        int kcb = lane >> 4;
#pragma unroll
        for (int mf = 0; mf < 4; ++mf) {
            int row = wm + mf * 16 + rl;
#pragma unroll
            for (int kq = 0; kq < 2; ++kq)
                adA[mf][kq] = sb + aoff(row, kq * 2 + kcb);
        }
#pragma unroll
        for (int nf2 = 0; nf2 < 2; ++nf2) {
            int cb = (wn >> 3) + nf2 * 2 + (lane >> 4);
#pragma unroll
            for (int kq = 0; kq < 2; ++kq) {
                int k = kq * 16 + rl;
                adB[nf2][kq] = sb + OFF_B16 + boff(k, cb, 256);
            }
        }
    }

    float acc[4][4][4];
#pragma unroll
    for (int a = 0; a < 4; ++a)
#pragma unroll
        for (int b = 0; b < 4; ++b)
#pragma unroll
            for (int c = 0; c < 4; ++c) acc[a][b][c] = 0.f;

    const int nIter = K / 32;

    DN_ISSUE(0, 0);
    DN_ISSUE(1, 1);
    DN_ISSUE(2, 2);
    CP_WAIT2;
    __syncthreads();
    CVT_DN(0, 0);

    int c3 = 1, i4 = 0, bb = 0, j4 = 3, j3 = 0;
    for (int it = 0; it < nIter; ++it) {
        CP_WAIT1;
        __syncthreads();
        if (it + 3 < nIter) { DN_ISSUE(j4, j3); } else { CP_COMMIT; }
        if (it + 1 < nIter) CVT_DN(c3, bb ^ 1);

        uint32_t poA = (uint32_t)i4 * 8192u;
        uint32_t poB = (uint32_t)bb * 8192u;
#pragma unroll
        for (int kq = 0; kq < 2; ++kq) {
            uint32_t b0[4], b1[4];
            ldsm4t(b0, adB[0][kq] + poB);
            ldsm4t(b1, adB[1][kq] + poB);
#pragma unroll
            for (int mf = 0; mf < 4; ++mf) {
                uint32_t a[4];
                ldsm4(a, adA[mf][kq] + poA);
                mma16(acc[mf][0], a, b0[0], b0[1]);
                mma16(acc[mf][1], a, b0[2], b0[3]);
                mma16(acc[mf][2], a, b1[0], b1[1]);
                mma16(acc[mf][3], a, b1[2], b1[3]);
            }
        }
        if (++c3 == 3) c3 = 0;
        if (++i4 == 4) i4 = 0;
        bb ^= 1;
        if (++j4 == 4) j4 = 0;
        if (++j3 == 3) j3 = 0;
    }

    // epilogue
#pragma unroll
    for (int mf = 0; mf < 4; ++mf)
#pragma unroll
        for (int h = 0; h < 2; ++h) {
            int rl = wm + mf * 16 + g + h * 8;
            int gi = row0 + rl;
            if (gi >= cnt) continue;
            int idx = list ? list[e * TT + gi] : gi;
            float s = 1.f;
            float* Cr;
            if (ATOMIC) {
                if (rowScale) s = rowScale[idx];
                Cr = C + (size_t)(idx / kdiv) * N + col0;
            } else {
                Cr = C + (size_t)idx * N + col0;
            }
#pragma unroll
            for (int nf = 0; nf < 4; ++nf) {
                int col = wn + nf * 8 + 2 * l4;
                float v0 = acc[mf][nf][2 * h + 0];
                float v1 = acc[mf][nf][2 * h + 1];
                if (ATOMIC) {
                    red2(Cr + col, v0 * s, v1 * s);
                } else {
                    *(float2*)(Cr + col) = make_float2(v0, v1);
                }
            }
        }
#undef DN_ISSUE
#undef CVT_DN
}

// ---------------- launch ------------------------------------------------------
extern "C" void kernel_launch(void* const* d_in, const int* in_sizes, int n_in,
                              void* d_out, int out_size)
{
    const float* x      = (const float*)d_in[0];
    const float* wr     = (const float*)d_in[1];
    const float* bias   = (const float*)d_in[2];
    const float* gate_w = (const float*)d_in[3];
    const float* up_w   = (const float*)d_in[4];
    const float* down_w = (const float*)d_in[5];
    const float* shg    = (const float*)d_in[6];
    const float* shu    = (const float*)d_in[7];
    const float* shd    = (const float*)d_in[8];
    float* out = (float*)d_out;

    void *p_act, *p_shact, *p_w, *p_cnt, *p_list, *p_xh;
    cudaGetSymbolAddress(&p_act,   g_act);
    cudaGetSymbolAddress(&p_shact, g_shact);
    cudaGetSymbolAddress(&p_w,     g_topkw);
    cudaGetSymbolAddress(&p_cnt,   g_cnt);
    cudaGetSymbolAddress(&p_list,  g_list);
    cudaGetSymbolAddress(&p_xh,    g_x_h);

    cudaFuncSetAttribute(gu_hgemm,    cudaFuncAttributeMaxDynamicSharedMemorySize, SMEM_SZ);
    cudaFuncSetAttribute(dn_hgemm<0>, cudaFuncAttributeMaxDynamicSharedMemorySize, SMEM_SZ);
    cudaFuncSetAttribute(dn_hgemm<1>, cudaFuncAttributeMaxDynamicSharedMemorySize, SMEM_SZ);

    cudaStream_t s1;
    cudaStreamCreateWithFlags(&s1, cudaStreamNonBlocking);
    cudaEvent_t evFork, evX, evRt, evGu0, evDn0;
    cudaEventCreateWithFlags(&evFork, cudaEventDisableTiming);
    cudaEventCreateWithFlags(&evX,    cudaEventDisableTiming);
    cudaEventCreateWithFlags(&evRt,   cudaEventDisableTiming);
    cudaEventCreateWithFlags(&evGu0,  cudaEventDisableTiming);
    cudaEventCreateWithFlags(&evDn0,  cudaEventDisableTiming);

    const int HEX = EE / 2;                         // 16 experts per half
    const size_t wofs = (size_t)HEX * HH * MI;      // gate/up weight offset
    const size_t dofs = (size_t)HEX * MI * HH;      // down weight offset

    cudaEventRecord(evFork, 0);
    cudaStreamWaitEvent(s1, evFork, 0);

    // ---- s1: zero out, router ----
    cudaMemsetAsync(out, 0, (size_t)TT * HH * sizeof(float), s1);
    zero_cnt_kernel<<<1, 32, 0, s1>>>();
    router_kernel<<<TT / 8, 256, 0, s1>>>(x, wr, bias);
    cudaEventRecord(evRt, s1);

    // ---- s0: convert x to fp16 ----
    cvt_kernel<<<(N_X / 8 + 255) / 256, 256>>>(
        (const float4*)x, (uint4*)p_xh, N_X / 8);
    cudaEventRecord(evX, 0);

    // ---- s0: routed gu, first half (experts 0..15) ----
    cudaStreamWaitEvent(0, evRt, 0);   // router lists + memset (transitive)
    gu_hgemm<<<dim3(MI / 64, TT / 128, HEX), 256, SMEM_SZ>>>(
        (const __half*)p_xh, gate_w, up_w, (__half*)p_act,
        (const int*)p_list, (const int*)p_cnt, HH, MI, KTOP, 0);
    cudaEventRecord(evGu0, 0);

    // ---- s1: shared chain, then routed dn first half ----
    cudaStreamWaitEvent(s1, evX, 0);
    gu_hgemm<<<dim3(MSHD / 64, TT / 128, 1), 256, SMEM_SZ, s1>>>(
        (const __half*)p_xh, shg, shu, (__half*)p_shact,
        nullptr, nullptr, HH, MSHD, 1, TT);
    dn_hgemm<1><<<dim3(HH / 128, TT / 128, 1), 256, SMEM_SZ, s1>>>(
        (const __half*)p_shact, shd, out,
        nullptr, nullptr, nullptr, MSHD, HH, TT, 1);
    cudaStreamWaitEvent(s1, evGu0, 0);
    dn_hgemm<1><<<dim3(HH / 128, TT / 128, HEX), 256, SMEM_SZ, s1>>>(
        (const __half*)p_act, down_w, out,
        (const int*)p_list, (const int*)p_cnt, (const float*)p_w,
        MI, HH, 0, KTOP);
    cudaEventRecord(evDn0, s1);

    // ---- s0: routed gu second half, then routed dn second half ----
    gu_hgemm<<<dim3(MI / 64, TT / 128, HEX), 256, SMEM_SZ>>>(
        (const __half*)p_xh, gate_w + wofs, up_w + wofs, (__half*)p_act,
        (const int*)p_list + HEX * TT, (const int*)p_cnt + HEX,
        HH, MI, KTOP, 0);
    dn_hgemm<1><<<dim3(HH / 128, TT / 128, HEX), 256, SMEM_SZ>>>(
        (const __half*)p_act, down_w + dofs, out,
        (const int*)p_list + HEX * TT, (const int*)p_cnt + HEX,
        (const float*)p_w, MI, HH, 0, KTOP);

    // join s1 into capture
    cudaStreamWaitEvent(0, evDn0, 0);
}